// round 14
// baseline (speedup 1.0000x reference)
#include <cuda_runtime.h>
#include <cuda_bf16.h>

#define Bb 4
#define Hh 200
#define Ww 200
#define Tt 5
#define C4 16                 // float4 per 64-channel dim
#define PIX_F4 (Tt * C4)      // 80 float4 per (b,h,w) pixel

// Tile = 8(w) x 2(h) pixels x 16 c4 = 256 threads. Linear decode:
// 25 tiles across w, 100 tile-rows, 2500 per batch, 10000 total.
#define TILES_X 25
#define TILES_PER_BATCH 2500
#define TOTAL_TILES (Bb * TILES_PER_BATCH)   // 10000
#define PERSIST_BLOCKS 444    // one wave: 3 blocks/SM x 148 SMs

__global__ __launch_bounds__(256, 3) void align_bev_v14(
    const float4* __restrict__ in,
    const float*  __restrict__ ego,
    float4* __restrict__ out)
{
    // per-batch affine constants: (c, s, Kx, Ky)
    __shared__ float4 cst[Bb];

    if (threadIdx.x < Bb) {
        int b = threadIdx.x;
        float dx   = ego[3 * b + 0];
        float dy   = ego[3 * b + 1];
        float dyaw = ego[3 * b + 2];
        float s, c;
        sincosf(dyaw, &s, &c);
        // ixv = c*w + s*h + Kx ; iyv = -s*w + c*h + Ky   (H=W=200)
        float Kx = 99.5f - 99.5f * (c + s) - (c * dx + s * dy);
        float Ky = 99.5f + 99.5f * (s - c) + (s * dx - c * dy);
        cst[b] = make_float4(c, s, Kx, Ky);
    }
    __syncthreads();

    int c4 = threadIdx.x & 15;
    int px = threadIdx.x >> 4;              // 0..15 pixel within tile
    int pw = px & 7;
    int ph = px >> 3;

    #pragma unroll 2
    for (int bid = blockIdx.x; bid < TOTAL_TILES; bid += PERSIST_BLOCKS) {
        // ---- minimal linear tile decode ----
        int b   = bid / TILES_PER_BATCH;
        int rr  = bid - b * TILES_PER_BATCH;
        int trow = rr / TILES_X;            // 0..99
        int tcol = rr - trow * TILES_X;     // 0..24

        int w = tcol * 8 + pw;
        int h = trow * 2 + ph;
        int pix = (b * Hh + h) * Ww + w;

        float4 k = cst[b];                  // broadcast LDS: c, s, Kx, Ky
        float c = k.x, s = k.y;

        // ---- per-pixel map: 4 FMAs ----
        float wf = (float)w, hf = (float)h;
        float ixv = fmaf(c, wf, fmaf(s, hf, k.z));
        float iyv = fmaf(-s, wf, fmaf(c, hf, k.w));

        float ix0f = floorf(ixv);
        float iy0f = floorf(iyv);
        float wx1 = ixv - ix0f, wx0 = 1.0f - wx1;
        float wy1 = iyv - iy0f, wy0 = 1.0f - wy1;
        float ix1f = ix0f + 1.0f;
        float iy1f = iy0f + 1.0f;

        float mx0 = (ix0f >= 0.0f && ix0f <= (float)(Ww - 1)) ? 1.0f : 0.0f;
        float mx1 = (ix1f >= 0.0f && ix1f <= (float)(Ww - 1)) ? 1.0f : 0.0f;
        float my0 = (iy0f >= 0.0f && iy0f <= (float)(Hh - 1)) ? 1.0f : 0.0f;
        float my1 = (iy1f >= 0.0f && iy1f <= (float)(Hh - 1)) ? 1.0f : 0.0f;

        int x0 = (int)fminf(fmaxf(ix0f, 0.0f), (float)(Ww - 1));
        int x1 = (int)fminf(fmaxf(ix1f, 0.0f), (float)(Ww - 1));
        int y0 = (int)fminf(fmaxf(iy0f, 0.0f), (float)(Hh - 1));
        int y1 = (int)fminf(fmaxf(iy1f, 0.0f), (float)(Hh - 1));

        float w00 = wy0 * wx0 * (my0 * mx0);
        float w01 = wy0 * wx1 * (my0 * mx1);
        float w10 = wy1 * wx0 * (my1 * mx0);
        float w11 = wy1 * wx1 * (my1 * mx1);

        int baseB = b * (Hh * Ww);
        int o00 = (baseB + y0 * Ww + x0) * PIX_F4 + c4;
        int o01 = (baseB + y0 * Ww + x1) * PIX_F4 + c4;
        int o10 = (baseB + y1 * Ww + x0) * PIX_F4 + c4;
        int o11 = (baseB + y1 * Ww + x1) * PIX_F4 + c4;

        int outbase = pix * PIX_F4 + c4;
        int tc4 = (Tt - 1) * C4;

        // ---- front-batched loads (17) ----
        float4 a00 = __ldg(&in[o00 +  0]);
        float4 a01 = __ldg(&in[o01 +  0]);
        float4 a10 = __ldg(&in[o10 +  0]);
        float4 a11 = __ldg(&in[o11 +  0]);
        float4 b00 = __ldg(&in[o00 + 16]);
        float4 b01 = __ldg(&in[o01 + 16]);
        float4 b10 = __ldg(&in[o10 + 16]);
        float4 b11 = __ldg(&in[o11 + 16]);
        float4 e00 = __ldg(&in[o00 + 32]);
        float4 e01 = __ldg(&in[o01 + 32]);
        float4 e10 = __ldg(&in[o10 + 32]);
        float4 e11 = __ldg(&in[o11 + 32]);
        float4 f00 = __ldg(&in[o00 + 48]);
        float4 f01 = __ldg(&in[o01 + 48]);
        float4 f10 = __ldg(&in[o10 + 48]);
        float4 f11 = __ldg(&in[o11 + 48]);
        float4 cur = __ldcs(&in[outbase + tc4]);

        // ---- blend + store ----
        float4 r0, r1, r2, r3;
        r0.x = w00*a00.x + w01*a01.x + w10*a10.x + w11*a11.x;
        r0.y = w00*a00.y + w01*a01.y + w10*a10.y + w11*a11.y;
        r0.z = w00*a00.z + w01*a01.z + w10*a10.z + w11*a11.z;
        r0.w = w00*a00.w + w01*a01.w + w10*a10.w + w11*a11.w;
        r1.x = w00*b00.x + w01*b01.x + w10*b10.x + w11*b11.x;
        r1.y = w00*b00.y + w01*b01.y + w10*b10.y + w11*b11.y;
        r1.z = w00*b00.z + w01*b01.z + w10*b10.z + w11*b11.z;
        r1.w = w00*b00.w + w01*b01.w + w10*b10.w + w11*b11.w;
        __stcs(&out[outbase +  0], r0);
        __stcs(&out[outbase + 16], r1);

        r2.x = w00*e00.x + w01*e01.x + w10*e10.x + w11*e11.x;
        r2.y = w00*e00.y + w01*e01.y + w10*e10.y + w11*e11.y;
        r2.z = w00*e00.z + w01*e01.z + w10*e10.z + w11*e11.z;
        r2.w = w00*e00.w + w01*e01.w + w10*e10.w + w11*e11.w;
        r3.x = w00*f00.x + w01*f01.x + w10*f10.x + w11*f11.x;
        r3.y = w00*f00.y + w01*f01.y + w10*f10.y + w11*f11.y;
        r3.z = w00*f00.z + w01*f01.z + w10*f10.z + w11*f11.z;
        r3.w = w00*f00.w + w01*f01.w + w10*f10.w + w11*f11.w;
        __stcs(&out[outbase + 32], r2);
        __stcs(&out[outbase + 48], r3);

        __stcs(&out[outbase + tc4], cur);
    }
}

extern "C" void kernel_launch(void* const* d_in, const int* in_sizes, int n_in,
                              void* d_out, int out_size)
{
    const float4* in  = (const float4*)d_in[0];   // raw_bev_cache (4,200,200,5,64) f32
    const float*  ego = (const float*)d_in[1];    // delta_ego_motion (4,3) f32
    float4* out = (float4*)d_out;

    align_bev_v14<<<PERSIST_BLOCKS, 256>>>(in, ego, out);
}

// round 15
// speedup vs baseline: 1.0060x; 1.0060x over previous
#include <cuda_runtime.h>
#include <cuda_bf16.h>

#define Bb 4
#define Hh 200
#define Ww 200
#define Tt 5
#define C4 16                 // float4 per 64-channel dim
#define PIX_F4 (Tt * C4)      // 80 float4 per (b,h,w) pixel

// Tile = 8(w) x 2(h) pixels x 16 c4 = 256 threads. Linear decode:
// 25 tiles across w, 100 tile-rows, 2500 per batch, 10000 total.
#define TILES_X 25
#define TILES_PER_BATCH 2500
#define TOTAL_TILES (Bb * TILES_PER_BATCH)   // 10000
#define PERSIST_BLOCKS 592    // one wave: 4 blocks/SM x 148 SMs

// Reused corner load: keep resident in L1 against streaming churn.
__device__ __forceinline__ float4 ldg_evict_last(const float4* p) {
    float4 v;
    asm volatile("ld.global.nc.L1::evict_last.v4.f32 {%0,%1,%2,%3}, [%4];"
                 : "=f"(v.x), "=f"(v.y), "=f"(v.z), "=f"(v.w)
                 : "l"(p));
    return v;
}

__global__ __launch_bounds__(256, 4) void align_bev_v15(
    const float4* __restrict__ in,
    const float*  __restrict__ ego,
    float4* __restrict__ out)
{
    // per-batch affine constants: (c, s, Kx, Ky)
    __shared__ float4 cst[Bb];

    if (threadIdx.x < Bb) {
        int b = threadIdx.x;
        float dx   = ego[3 * b + 0];
        float dy   = ego[3 * b + 1];
        float dyaw = ego[3 * b + 2];
        float s, c;
        sincosf(dyaw, &s, &c);
        // ixv = c*w + s*h + Kx ; iyv = -s*w + c*h + Ky   (H=W=200)
        float Kx = 99.5f - 99.5f * (c + s) - (c * dx + s * dy);
        float Ky = 99.5f + 99.5f * (s - c) + (s * dx - c * dy);
        cst[b] = make_float4(c, s, Kx, Ky);
    }
    __syncthreads();

    int c4 = threadIdx.x & 15;
    int px = threadIdx.x >> 4;              // 0..15 pixel within tile
    int pw = px & 7;
    int ph = px >> 3;

    #pragma unroll 1
    for (int bid = blockIdx.x; bid < TOTAL_TILES; bid += PERSIST_BLOCKS) {
        // ---- minimal linear tile decode ----
        int b    = bid / TILES_PER_BATCH;
        int rr   = bid - b * TILES_PER_BATCH;
        int trow = rr / TILES_X;            // 0..99
        int tcol = rr - trow * TILES_X;     // 0..24

        int w = tcol * 8 + pw;
        int h = trow * 2 + ph;
        int pix = (b * Hh + h) * Ww + w;

        float4 k = cst[b];                  // broadcast LDS: c, s, Kx, Ky
        float c = k.x, s = k.y;

        // ---- per-pixel map: 4 FMAs ----
        float wf = (float)w, hf = (float)h;
        float ixv = fmaf(c, wf, fmaf(s, hf, k.z));
        float iyv = fmaf(-s, wf, fmaf(c, hf, k.w));

        float ix0f = floorf(ixv);
        float iy0f = floorf(iyv);
        float wx1 = ixv - ix0f, wx0 = 1.0f - wx1;
        float wy1 = iyv - iy0f, wy0 = 1.0f - wy1;
        float ix1f = ix0f + 1.0f;
        float iy1f = iy0f + 1.0f;

        float mx0 = (ix0f >= 0.0f && ix0f <= (float)(Ww - 1)) ? 1.0f : 0.0f;
        float mx1 = (ix1f >= 0.0f && ix1f <= (float)(Ww - 1)) ? 1.0f : 0.0f;
        float my0 = (iy0f >= 0.0f && iy0f <= (float)(Hh - 1)) ? 1.0f : 0.0f;
        float my1 = (iy1f >= 0.0f && iy1f <= (float)(Hh - 1)) ? 1.0f : 0.0f;

        int x0 = (int)fminf(fmaxf(ix0f, 0.0f), (float)(Ww - 1));
        int x1 = (int)fminf(fmaxf(ix1f, 0.0f), (float)(Ww - 1));
        int y0 = (int)fminf(fmaxf(iy0f, 0.0f), (float)(Hh - 1));
        int y1 = (int)fminf(fmaxf(iy1f, 0.0f), (float)(Hh - 1));

        float w00 = wy0 * wx0 * (my0 * mx0);
        float w01 = wy0 * wx1 * (my0 * mx1);
        float w10 = wy1 * wx0 * (my1 * mx0);
        float w11 = wy1 * wx1 * (my1 * mx1);

        int baseB = b * (Hh * Ww);
        int o00 = (baseB + y0 * Ww + x0) * PIX_F4 + c4;
        int o01 = (baseB + y0 * Ww + x1) * PIX_F4 + c4;
        int o10 = (baseB + y1 * Ww + x0) * PIX_F4 + c4;
        int o11 = (baseB + y1 * Ww + x1) * PIX_F4 + c4;

        int outbase = pix * PIX_F4 + c4;
        int tc4 = (Tt - 1) * C4;

        // ---- front-batched loads (17); corner loads pinned evict_last ----
        float4 a00 = ldg_evict_last(&in[o00 +  0]);
        float4 a01 = ldg_evict_last(&in[o01 +  0]);
        float4 a10 = ldg_evict_last(&in[o10 +  0]);
        float4 a11 = ldg_evict_last(&in[o11 +  0]);
        float4 b00 = ldg_evict_last(&in[o00 + 16]);
        float4 b01 = ldg_evict_last(&in[o01 + 16]);
        float4 b10 = ldg_evict_last(&in[o10 + 16]);
        float4 b11 = ldg_evict_last(&in[o11 + 16]);
        float4 e00 = ldg_evict_last(&in[o00 + 32]);
        float4 e01 = ldg_evict_last(&in[o01 + 32]);
        float4 e10 = ldg_evict_last(&in[o10 + 32]);
        float4 e11 = ldg_evict_last(&in[o11 + 32]);
        float4 f00 = ldg_evict_last(&in[o00 + 48]);
        float4 f01 = ldg_evict_last(&in[o01 + 48]);
        float4 f10 = ldg_evict_last(&in[o10 + 48]);
        float4 f11 = ldg_evict_last(&in[o11 + 48]);
        float4 cur = __ldcs(&in[outbase + tc4]);

        // ---- blend + store ----
        float4 r0, r1, r2, r3;
        r0.x = w00*a00.x + w01*a01.x + w10*a10.x + w11*a11.x;
        r0.y = w00*a00.y + w01*a01.y + w10*a10.y + w11*a11.y;
        r0.z = w00*a00.z + w01*a01.z + w10*a10.z + w11*a11.z;
        r0.w = w00*a00.w + w01*a01.w + w10*a10.w + w11*a11.w;
        r1.x = w00*b00.x + w01*b01.x + w10*b10.x + w11*b11.x;
        r1.y = w00*b00.y + w01*b01.y + w10*b10.y + w11*b11.y;
        r1.z = w00*b00.z + w01*b01.z + w10*b10.z + w11*b11.z;
        r1.w = w00*b00.w + w01*b01.w + w10*b10.w + w11*b11.w;
        __stcs(&out[outbase +  0], r0);
        __stcs(&out[outbase + 16], r1);

        r2.x = w00*e00.x + w01*e01.x + w10*e10.x + w11*e11.x;
        r2.y = w00*e00.y + w01*e01.y + w10*e10.y + w11*e11.y;
        r2.z = w00*e00.z + w01*e01.z + w10*e10.z + w11*e11.z;
        r2.w = w00*e00.w + w01*e01.w + w10*e10.w + w11*e11.w;
        r3.x = w00*f00.x + w01*f01.x + w10*f10.x + w11*f11.x;
        r3.y = w00*f00.y + w01*f01.y + w10*f10.y + w11*f11.y;
        r3.z = w00*f00.z + w01*f01.z + w10*f10.z + w11*f11.z;
        r3.w = w00*f00.w + w01*f01.w + w10*f10.w + w11*f11.w;
        __stcs(&out[outbase + 32], r2);
        __stcs(&out[outbase + 48], r3);

        __stcs(&out[outbase + tc4], cur);
    }
}

extern "C" void kernel_launch(void* const* d_in, const int* in_sizes, int n_in,
                              void* d_out, int out_size)
{
    const float4* in  = (const float4*)d_in[0];   // raw_bev_cache (4,200,200,5,64) f32
    const float*  ego = (const float*)d_in[1];    // delta_ego_motion (4,3) f32
    float4* out = (float4*)d_out;

    align_bev_v15<<<PERSIST_BLOCKS, 256>>>(in, ego, out);
}